// round 9
// baseline (speedup 1.0000x reference)
#include <cuda_runtime.h>

// SpatialDeformer3D via SMEM-tiled trilinear gather, v6:
//  - 4 voxels per thread along d: def read as 3x float4 (LDG.128), output
//    written as one float4 (STG.128), 4 independent tap chains per thread
//  - same 8x16x32 tile, +/-2 halo, fast path = base + 8 immediate-offset LDS
//  - rare fallback: exact reference math with clamps + global gathers
//
//   X:           (2, 160, 192, 160, 2)  float32
//   deformation: (2, 160, 192, 160, 3)  float32
//   out:         (2, 160, 192, 160, 1)  float32

#define BB 2
#define HH 160
#define WW 192
#define DD 160
#define WD (WW * DD)

#define TH 8
#define TW 16
#define TD 32
#define RLO 2              // halo below; +3 above (x1=x0+1) => extent T+5
#define HS (TH + 5)        // 13
#define WS (TW + 5)        // 21
#define DS (TD + 5)        // 37
#define NROWS (HS * WS)    // 273
#define SVOL (NROWS * DS)  // 10101 floats = 40404 B

__global__ __launch_bounds__(512, 2) void deform3d_tile6_kernel(
    const float* __restrict__ X,
    const float* __restrict__ def,
    float* __restrict__ out)
{
    extern __shared__ float s[];

    const int b  = blockIdx.z / (HH / TH);
    const int hz = blockIdx.z % (HH / TH);
    const int h0 = hz * TH;
    const int w0 = blockIdx.y * TW;
    const int d0 = blockIdx.x * TD;

    const int tid    = threadIdx.x;          // 512 flat
    const int lane   = tid & 31;
    const int warpId = tid >> 5;             // 16 warps

    const int dg = tid & 7;                  // d-group: 4 voxels each
    const int wy = (tid >> 3) & 15;          // w
    const int hg = tid >> 7;                 // 0..3 -> 2 h values each

    const float* Xb = X + (size_t)b * (HH * WW * DD * 2);

    const int yb = h0 - RLO;
    const int xb = w0 - RLO;
    const int zb = d0 - RLO;

    const int d = d0 + dg * 4;               // first of 4 consecutive d
    const int w = w0 + wy;
    const int hbase = h0 + hg * 2;

    const float4* __restrict__ def4 = (const float4*)def;

    const int voxA = ((b * HH + hbase) * WW + w) * DD + d;   // multiple of 4
    const int voxB = voxA + WD;

    // ---- Prologue: def loads for h-iteration 0 (hidden by the fill). ----
    size_t fiA = (size_t)voxA * 3 / 4;
    float4 a0 = __ldg(def4 + fiA + 0);
    float4 a1 = __ldg(def4 + fiA + 1);
    float4 a2 = __ldg(def4 + fiA + 2);

    // ---- SMEM fill: one warp per (hy,wx) row, div-free decomposition ----
    {
        const int ezA = min(max(zb + lane, 0), DD - 1) * 2;
        const int ezB = min(max(zb + lane + 32, 0), DD - 1) * 2;

        int hy = 0, wx = warpId;             // warpId < 16 < WS
        for (int row = warpId; row < NROWS; row += 16) {
            int gy = min(max(yb + hy, 0), HH - 1);
            int gx = min(max(xb + wx, 0), WW - 1);
            const float* src = Xb + (size_t)(gy * WW + gx) * (DD * 2);
            float* dst = s + row * DS;
            dst[lane] = __ldg(src + ezA);
            if (lane < DS - 32)
                dst[lane + 32] = __ldg(src + ezB);
            wx += 16;
            if (wx >= WS) { wx -= WS; hy++; }
        }
    }
    __syncthreads();

    // Fast-path bounds: corner index c0 must satisfy clip-identity AND
    // in-tile:  c0 in [max(0, base), min(base + S - 2, LIM - 2)].
    const int loY = max(0, yb), rngY = min(yb + HS - 2, HH - 2) - loY;
    const int loX = max(0, xb), rngX = min(xb + WS - 2, WW - 2) - loX;
    const int loZ = max(0, zb), rngZ = min(zb + DS - 2, DD - 2) - loZ;

    const float wf = (float)w;

    // Issue h-iteration 1 def loads now; overlap with iteration-0 compute.
    size_t fiB = (size_t)voxB * 3 / 4;
    float4 b0 = __ldg(def4 + fiB + 0);
    float4 b1 = __ldg(def4 + fiB + 1);
    float4 b2 = __ldg(def4 + fiB + 2);

    #pragma unroll
    for (int it = 0; it < 2; it++) {
        float4 f0, f1, f2;
        int vox, h;
        if (it == 0) { f0 = a0; f1 = a1; f2 = a2; vox = voxA; h = hbase; }
        else         { f0 = b0; f1 = b1; f2 = b2; vox = voxB; h = hbase + 1; }

        // Unpack AoS: voxel k has (dx,dy,dz) at floats 3k..3k+2.
        float dxs[4] = { f0.x, f0.w, f1.z, f2.y };
        float dys[4] = { f0.y, f1.x, f1.w, f2.z };
        float dzs[4] = { f0.z, f1.y, f2.x, f2.w };

        const float hf = (float)h;
        float resv[4];

        #pragma unroll
        for (int k = 0; k < 4; k++) {
            float x = wf + dxs[k];                 // def[...,0] -> W axis
            float y = hf + dys[k];                 // def[...,1] -> H axis
            float z = (float)(d + k) + dzs[k];     // def[...,2] -> D axis

            int x0 = __float2int_rd(x);
            int y0 = __float2int_rd(y);
            int z0 = __float2int_rd(z);

            bool fastp = ((unsigned)(y0 - loY) <= (unsigned)rngY) &
                         ((unsigned)(x0 - loX) <= (unsigned)rngX) &
                         ((unsigned)(z0 - loZ) <= (unsigned)rngZ);

            float res;
            if (fastp) {
                // clip == identity: x1 = x0+1 etc., all taps in SMEM tile.
                float x0f = (float)x0, y0f = (float)y0, z0f = (float)z0;
                float wx1 = x - x0f, wx0 = (x0f + 1.0f) - x;
                float wy1 = y - y0f, wy0 = (y0f + 1.0f) - y;
                float wz1 = z - z0f, wz0 = (z0f + 1.0f) - z;

                int base = ((y0 - yb) * WS + (x0 - xb)) * DS + (z0 - zb);

                float p000 = s[base];
                float p001 = s[base + 1];
                float p010 = s[base + DS];
                float p011 = s[base + DS + 1];
                float p100 = s[base + WS * DS];
                float p101 = s[base + WS * DS + 1];
                float p110 = s[base + WS * DS + DS];
                float p111 = s[base + WS * DS + DS + 1];

                res = wy0 * (wx0 * (wz0 * p000 + wz1 * p001) +
                             wx1 * (wz0 * p010 + wz1 * p011)) +
                      wy1 * (wx0 * (wz0 * p100 + wz1 * p101) +
                             wx1 * (wz0 * p110 + wz1 * p111));
            } else {
                // Exact reference path: clip each corner independently;
                // weights from CLIPPED coords so out-of-range dims cancel.
                int x1 = x0 + 1, y1 = y0 + 1, z1 = z0 + 1;
                x0 = min(max(x0, 0), WW - 1);  x1 = min(max(x1, 0), WW - 1);
                y0 = min(max(y0, 0), HH - 1);  y1 = min(max(y1, 0), HH - 1);
                z0 = min(max(z0, 0), DD - 1);  z1 = min(max(z1, 0), DD - 1);

                float wx0 = (float)x1 - x, wx1 = x - (float)x0;
                float wy0 = (float)y1 - y, wy1 = y - (float)y0;
                float wz0 = (float)z1 - z, wz1 = z - (float)z0;

                int i00 = (y0 * WW + x0) * (DD * 2);
                int i01 = (y0 * WW + x1) * (DD * 2);
                int i10 = (y1 * WW + x0) * (DD * 2);
                int i11 = (y1 * WW + x1) * (DD * 2);
                int z0e = z0 * 2, z1e = z1 * 2;
                float p000 = __ldg(Xb + i00 + z0e), p001 = __ldg(Xb + i00 + z1e);
                float p010 = __ldg(Xb + i01 + z0e), p011 = __ldg(Xb + i01 + z1e);
                float p100 = __ldg(Xb + i10 + z0e), p101 = __ldg(Xb + i10 + z1e);
                float p110 = __ldg(Xb + i11 + z0e), p111 = __ldg(Xb + i11 + z1e);

                res = wy0 * (wx0 * (wz0 * p000 + wz1 * p001) +
                             wx1 * (wz0 * p010 + wz1 * p011)) +
                      wy1 * (wx0 * (wz0 * p100 + wz1 * p101) +
                             wx1 * (wz0 * p110 + wz1 * p111));
            }
            resv[k] = res;
        }

        float4 o;
        o.x = resv[0]; o.y = resv[1]; o.z = resv[2]; o.w = resv[3];
        __stcs((float4*)(out + vox), o);   // streaming STG.128
    }
}

extern "C" void kernel_launch(void* const* d_in, const int* in_sizes, int n_in,
                              void* d_out, int out_size)
{
    const float* X   = (const float*)d_in[0];
    const float* def = (const float*)d_in[1];
    float* out = (float*)d_out;

    cudaFuncSetAttribute(deform3d_tile6_kernel,
                         cudaFuncAttributeMaxDynamicSharedMemorySize,
                         SVOL * (int)sizeof(float));

    dim3 grid(DD / TD, WW / TW, BB * (HH / TH));   // (5, 12, 40) = 2400 CTAs
    deform3d_tile6_kernel<<<grid, 512, SVOL * sizeof(float)>>>(X, def, out);
}

// round 10
// speedup vs baseline: 1.3506x; 1.3506x over previous
#include <cuda_runtime.h>

// SpatialDeformer3D via SMEM-tiled trilinear gather, v7:
//  - v5 structure (best: 87us), occupancy pushed to 4 CTAs/SM via
//    __launch_bounds__(512,4) (<=32 regs, 2048 thr/SM, smem 4x40.4KB fits)
//  - def stream loads via __ldcs (evict-first; keep L2 for X halo reuse)
//  - +/-2 halo, depth-2 def pipeline, fast path = base + 8 imm-offset LDS,
//    rare fallback = exact reference math with clamps + global gathers
//
//   X:           (2, 160, 192, 160, 2)  float32
//   deformation: (2, 160, 192, 160, 3)  float32
//   out:         (2, 160, 192, 160, 1)  float32

#define BB 2
#define HH 160
#define WW 192
#define DD 160
#define WD (WW * DD)

#define TH 8
#define TW 16
#define TD 32
#define RLO 2              // halo below; +3 above (x1=x0+1) => extent T+5
#define HS (TH + 5)        // 13
#define WS (TW + 5)        // 21
#define DS (TD + 5)        // 37
#define NROWS (HS * WS)    // 273
#define SVOL (NROWS * DS)  // 10101 floats = 40404 B

__global__ __launch_bounds__(512, 4) void deform3d_tile7_kernel(
    const float* __restrict__ X,
    const float* __restrict__ def,
    float* __restrict__ out)
{
    extern __shared__ float s[];

    const int b  = blockIdx.z / (HH / TH);
    const int hz = blockIdx.z % (HH / TH);
    const int h0 = hz * TH;
    const int w0 = blockIdx.y * TW;
    const int d0 = blockIdx.x * TD;

    const int lane   = threadIdx.x;   // 0..31 -> d
    const int wy     = threadIdx.y;   // 0..15 -> w
    const int warpId = wy;

    const float* Xb = X + (size_t)b * (HH * WW * DD * 2);

    const int yb = h0 - RLO;
    const int xb = w0 - RLO;
    const int zb = d0 - RLO;

    const int d = d0 + lane;
    const int w = w0 + wy;

    const int vox0 = ((b * HH + h0) * WW + w) * DD + d;

    // ---- Pipeline prologue: def loads for hh = 0, 1 issued before the
    //      SMEM fill so the fill hides their DRAM latency. ----
    float bx0, by0, bz0, bx1, by1, bz1;
    {
        const float* dp0 = def + (size_t)vox0 * 3;
        const float* dp1 = dp0 + (size_t)WD * 3;
        bx0 = __ldcs(dp0 + 0); by0 = __ldcs(dp0 + 1); bz0 = __ldcs(dp0 + 2);
        bx1 = __ldcs(dp1 + 0); by1 = __ldcs(dp1 + 1); bz1 = __ldcs(dp1 + 2);
    }

    // ---- SMEM fill: one warp per (hy,wx) row, div-free decomposition ----
    {
        const int ezA = min(max(zb + lane, 0), DD - 1) * 2;
        const int ezB = min(max(zb + lane + 32, 0), DD - 1) * 2;

        int hy = 0, wx = warpId;            // warpId < 16 < WS
        for (int row = warpId; row < NROWS; row += 16) {
            int gy = min(max(yb + hy, 0), HH - 1);
            int gx = min(max(xb + wx, 0), WW - 1);
            const float* src = Xb + (size_t)(gy * WW + gx) * (DD * 2);
            float* dst = s + row * DS;
            dst[lane] = __ldg(src + ezA);
            if (lane < DS - 32)
                dst[lane + 32] = __ldg(src + ezB);
            wx += 16;
            if (wx >= WS) { wx -= WS; hy++; }
        }
    }
    __syncthreads();

    // Fast-path bounds: corner index c0 must satisfy clip-identity AND
    // in-tile:  c0 in [max(0, base), min(base + S - 2, LIM - 2)].
    const int loY = max(0, yb), rngY = min(yb + HS - 2, HH - 2) - loY;
    const int loX = max(0, xb), rngX = min(xb + WS - 2, WW - 2) - loX;
    const int loZ = max(0, zb), rngZ = min(zb + DS - 2, DD - 2) - loZ;

    const float wf = (float)w;
    const float df = (float)d;

    int vox = vox0;
    const float* dpn = def + ((size_t)vox0 + (size_t)2 * WD) * 3; // hh+2 loads

    #pragma unroll
    for (int hh = 0; hh < TH; hh++, vox += WD) {
        // Consume the stage loaded 2 iterations ago.
        float dx, dy, dzv;
        if ((hh & 1) == 0) { dx = bx0; dy = by0; dzv = bz0; }
        else               { dx = bx1; dy = by1; dzv = bz1; }

        // Refill this stage with iteration hh+2.
        if (hh < TH - 2) {
            float nx = __ldcs(dpn + 0);
            float ny = __ldcs(dpn + 1);
            float nz = __ldcs(dpn + 2);
            if ((hh & 1) == 0) { bx0 = nx; by0 = ny; bz0 = nz; }
            else               { bx1 = nx; by1 = ny; bz1 = nz; }
            dpn += (size_t)WD * 3;
        }

        const int h = h0 + hh;

        float x = wf + dx;          // def[...,0] -> W axis
        float y = (float)h + dy;    // def[...,1] -> H axis
        float z = df + dzv;         // def[...,2] -> D axis

        int x0 = __float2int_rd(x);
        int y0 = __float2int_rd(y);
        int z0 = __float2int_rd(z);

        bool fast = ((unsigned)(y0 - loY) <= (unsigned)rngY) &
                    ((unsigned)(x0 - loX) <= (unsigned)rngX) &
                    ((unsigned)(z0 - loZ) <= (unsigned)rngZ);

        float res;
        if (fast) {
            // clip == identity here: x1 = x0+1 etc., all taps in SMEM tile.
            float x0f = (float)x0, y0f = (float)y0, z0f = (float)z0;
            float wx1 = x - x0f, wx0 = (x0f + 1.0f) - x;
            float wy1 = y - y0f, wy0 = (y0f + 1.0f) - y;
            float wz1 = z - z0f, wz0 = (z0f + 1.0f) - z;

            int base = ((y0 - yb) * WS + (x0 - xb)) * DS + (z0 - zb);

            float p000 = s[base];
            float p001 = s[base + 1];
            float p010 = s[base + DS];
            float p011 = s[base + DS + 1];
            float p100 = s[base + WS * DS];
            float p101 = s[base + WS * DS + 1];
            float p110 = s[base + WS * DS + DS];
            float p111 = s[base + WS * DS + DS + 1];

            res = wy0 * (wx0 * (wz0 * p000 + wz1 * p001) +
                         wx1 * (wz0 * p010 + wz1 * p011)) +
                  wy1 * (wx0 * (wz0 * p100 + wz1 * p101) +
                         wx1 * (wz0 * p110 + wz1 * p111));
        } else {
            // Exact reference path: clip each corner independently; weights
            // from CLIPPED coords so out-of-range dims cancel to zero.
            int x1 = x0 + 1, y1 = y0 + 1, z1 = z0 + 1;
            x0 = min(max(x0, 0), WW - 1);  x1 = min(max(x1, 0), WW - 1);
            y0 = min(max(y0, 0), HH - 1);  y1 = min(max(y1, 0), HH - 1);
            z0 = min(max(z0, 0), DD - 1);  z1 = min(max(z1, 0), DD - 1);

            float wx0 = (float)x1 - x, wx1 = x - (float)x0;
            float wy0 = (float)y1 - y, wy1 = y - (float)y0;
            float wz0 = (float)z1 - z, wz1 = z - (float)z0;

            int i00 = (y0 * WW + x0) * (DD * 2);
            int i01 = (y0 * WW + x1) * (DD * 2);
            int i10 = (y1 * WW + x0) * (DD * 2);
            int i11 = (y1 * WW + x1) * (DD * 2);
            int z0e = z0 * 2, z1e = z1 * 2;
            float p000 = __ldg(Xb + i00 + z0e), p001 = __ldg(Xb + i00 + z1e);
            float p010 = __ldg(Xb + i01 + z0e), p011 = __ldg(Xb + i01 + z1e);
            float p100 = __ldg(Xb + i10 + z0e), p101 = __ldg(Xb + i10 + z1e);
            float p110 = __ldg(Xb + i11 + z0e), p111 = __ldg(Xb + i11 + z1e);

            res = wy0 * (wx0 * (wz0 * p000 + wz1 * p001) +
                         wx1 * (wz0 * p010 + wz1 * p011)) +
                  wy1 * (wx0 * (wz0 * p100 + wz1 * p101) +
                         wx1 * (wz0 * p110 + wz1 * p111));
        }

        __stcs(out + vox, res);   // streaming store: keep L2 for X reuse
    }
}

extern "C" void kernel_launch(void* const* d_in, const int* in_sizes, int n_in,
                              void* d_out, int out_size)
{
    const float* X   = (const float*)d_in[0];
    const float* def = (const float*)d_in[1];
    float* out = (float*)d_out;

    cudaFuncSetAttribute(deform3d_tile7_kernel,
                         cudaFuncAttributeMaxDynamicSharedMemorySize,
                         SVOL * (int)sizeof(float));

    dim3 grid(DD / TD, WW / TW, BB * (HH / TH));   // (5, 12, 40) = 2400 CTAs
    dim3 block(32, 16, 1);                          // 512 threads
    deform3d_tile7_kernel<<<grid, block, SVOL * sizeof(float)>>>(X, def, out);
}